// round 11
// baseline (speedup 1.0000x reference)
#include <cuda_runtime.h>
#include <cstdint>
#include <algorithm>

// Problem constants
#define TPP  16
#define NCOL 513                      // 2*H*K + 1
#define EMBN 1000000
#define NTHREADS_TOTAL (1u << 20)     // NWORK/8: each thread handles 8 elements

struct PermParams {
    unsigned short posP[256];   // output column of +result[r]
    unsigned short posM[256];   // output column of -result[r]
    unsigned short posMid;      // output column of ori
    unsigned short pad;
};

// Rotation multipliers (1<<R) passed at runtime -> IMAD.WIDE on fma pipe
// (runtime values prevent ptxas strength-reducing back to SHF).
// Group order: GA rounds rot {13,15,26,6}; GB rounds rot {17,29,16,24}.
struct RotMuls { uint32_t a1, a2, a3, a4, b1, b2, b3, b4; };

// ---------------------------------------------------------------------------
// Threefry-2x32 (host side, for key/permutation derivation)
// ---------------------------------------------------------------------------
static inline uint32_t h_rotl32(uint32_t v, int r) {
    return (v << r) | (v >> (32 - r));
}
#define HTF_R(x0, x1, R) { x0 += x1; x1 = h_rotl32(x1, R) ^ x0; }
static void h_tf2x32(uint32_t k0, uint32_t k1, uint32_t x0, uint32_t x1,
                     uint32_t& o0, uint32_t& o1) {
    const uint32_t ks0 = k0, ks1 = k1, ks2 = k0 ^ k1 ^ 0x1BD11BDAu;
    x0 += ks0; x1 += ks1;
    HTF_R(x0, x1, 13) HTF_R(x0, x1, 15) HTF_R(x0, x1, 26) HTF_R(x0, x1, 6)
    x0 += ks1; x1 += ks2 + 1u;
    HTF_R(x0, x1, 17) HTF_R(x0, x1, 29) HTF_R(x0, x1, 16) HTF_R(x0, x1, 24)
    x0 += ks2; x1 += ks0 + 2u;
    HTF_R(x0, x1, 13) HTF_R(x0, x1, 15) HTF_R(x0, x1, 26) HTF_R(x0, x1, 6)
    x0 += ks0; x1 += ks1 + 3u;
    HTF_R(x0, x1, 17) HTF_R(x0, x1, 29) HTF_R(x0, x1, 16) HTF_R(x0, x1, 24)
    x0 += ks1; x1 += ks2 + 4u;
    HTF_R(x0, x1, 13) HTF_R(x0, x1, 15) HTF_R(x0, x1, 26) HTF_R(x0, x1, 6)
    x0 += ks2; x1 += ks0 + 5u;
    o0 = x0; o1 = x1;
}

// ---------------------------------------------------------------------------
// Main kernel: one thread per 8 adjacent elements (j = 8*tid + c, c=0..7).
// These share (level i, row t, rep k); tp0 in {0, 8}. Shared decode, shared
// gather, shared output columns, float4 stores. Eight interleaved Threefry
// chains (default occupancy: regs=32, occ ~86% -- R10 showed issue is fed by
// warp count here, not per-thread ILP).
// ALL 20 rotates via IMAD.WIDE (fma pipe) + fused (hi|lo)^x0 LOP3 (alu);
// adds left plain -- ptxas auto-alternates IMAD/IADD3 across pipes.
// Key injections folded into the next round's x0-add (IADD3).
// Level 0 (mask==0) skips Threefry entirely (block-uniform branch).
// Sign property: cand = ori ^ D with D < 2^16 keeps bit31 -> sign(cand) ==
// sign(ori) -> vp = +base; vm = base ^ signbit(cand | -cand).
// ---------------------------------------------------------------------------
__global__ void __launch_bounds__(256)
crit_kernel(const void* __restrict__ loc,
            const void* __restrict__ in1,
            const void* __restrict__ in2,
            float* __restrict__ out,
            uint32_t k2a, uint32_t k2b,
            RotMuls RM, PermParams P) {
    const uint32_t tid = blockIdx.x * 256u + threadIdx.x;
    const uint32_t j0 = tid * 8u;

    const uint32_t tp0 = j0 & 15u;          // 0 or 8
    const uint32_t k   = (j0 >> 4) & 15u;
    const uint32_t t   = (j0 >> 8) & 2047u;
    const uint32_t i   = j0 >> 19;

    // ---- input-layout probe (uniform broadcast loads, L1-hit) ----
    const uint4 A0 = ((const uint4*)in1)[0];
    const uint4 A1 = ((const uint4*)in1)[1];
    const uint4 B0 = ((const uint4*)in2)[0];
    const uint4 B1 = ((const uint4*)in2)[1];
    const uint4 L0 = ((const uint4*)loc)[0];
    const uint4 L1 = ((const uint4*)loc)[1];
    const bool aPos = (A0.x < (1u << 20));  // pos_idx < 2^20; uniform(0,1) bits larger
    const void*  posv = aPos ? in1 : in2;
    const float* nrmp = aPos ? (const float*)in2 : (const float*)in1;
    const uint4 Pw0 = aPos ? A0 : B0;
    const uint4 Pw1 = aPos ? A1 : B1;
    const bool pos64 = ((Pw0.y | Pw0.w | Pw1.y | Pw1.w) == 0u);
    const bool loc64 = (L0.y == 0u || L0.y == 0xFFFFFFFFu) &&
                       (L0.w == 0u || L0.w == 0xFFFFFFFFu) &&
                       (L1.y == 0u || L1.y == 0xFFFFFFFFu) &&
                       (L1.w == 0u || L1.w == 0xFFFFFFFFu);

    long long pidx = pos64 ? ((const long long*)posv)[t]
                           : (long long)((const int*)posv)[t];
    if (pidx < 0) pidx = 0;
    if (pidx >= EMBN) pidx = EMBN - 1;

    int ori[8];
    if (loc64) {
        const size_t base = (size_t)(pidx * TPP + tp0) >> 1;   // longlong2 index
        #pragma unroll
        for (int h = 0; h < 4; h++) {
            const longlong2 L = ((const longlong2*)loc)[base + h];
            ori[2*h]   = (int)L.x;
            ori[2*h+1] = (int)L.y;
        }
    } else {
        const size_t base = (size_t)(pidx * TPP + tp0) >> 2;   // int4 index
        const int4 La = ((const int4*)loc)[base];
        const int4 Lb = ((const int4*)loc)[base + 1];
        ori[0] = La.x; ori[1] = La.y; ori[2] = La.z; ori[3] = La.w;
        ori[4] = Lb.x; ori[5] = Lb.y; ori[6] = Lb.z; ori[7] = Lb.w;
    }
    const float nrm = nrmp[t];

    // ---- oct Threefry-2x32, 20 rounds, injections folded, all-wide rotates ----
    const uint32_t ks0 = k2a, ks1 = k2b, ks2 = k2a ^ k2b ^ 0x1BD11BDAu;
    const uint32_t c1B = ks2 + 1u, c2B = ks0 + 2u, c3B = ks1 + 3u,
                   c4B = ks2 + 4u, c5B = ks0 + 5u;

    uint32_t b2[8];
    #pragma unroll
    for (int c = 0; c < 8; c++) b2[c] = 0u;

#define RW_ALL(M) _Pragma("unroll") for (int c = 0; c < 8; c++) {              \
    x0[c] += x1[c];                                      /* IADD/IMAD (ptxas) */\
    uint64_t w_ = (uint64_t)x1[c] * (uint64_t)(M);       /* IMAD.WIDE */       \
    x1[c] = ((uint32_t)(w_ >> 32) | (uint32_t)w_) ^ x0[c]; /* fused LOP3 */    \
}
// Injection (cA into x0, cB into x1) folded into the round's x0-add: IADD3.
#define RW_INJ_ALL(M, cA, cB) _Pragma("unroll") for (int c = 0; c < 8; c++) {  \
    x1[c] += (cB);                                                             \
    x0[c] = (x0[c] + (cA)) + x1[c];                      /* IADD3 */           \
    uint64_t w_ = (uint64_t)x1[c] * (uint64_t)(M);                             \
    x1[c] = ((uint32_t)(w_ >> 32) | (uint32_t)w_) ^ x0[c];                     \
}
#define GA0            RW_ALL(RM.a1)             RW_ALL(RM.a2) RW_ALL(RM.a3) RW_ALL(RM.a4)
#define GA_INJ(cA, cB) RW_INJ_ALL(RM.a1, cA, cB) RW_ALL(RM.a2) RW_ALL(RM.a3) RW_ALL(RM.a4)
#define GB_INJ(cA, cB) RW_INJ_ALL(RM.b1, cA, cB) RW_ALL(RM.b2) RW_ALL(RM.b3) RW_ALL(RM.b4)

    if (i != 0) {       // level 0 has mask 0: Threefry output unused
        uint32_t x0[8], x1[8];
        #pragma unroll
        for (int c = 0; c < 8; c++) { x0[c] = ks0; x1[c] = (j0 + (uint32_t)c) + ks1; }
        GA0                      // rounds 1-4:   rot 13,15,26,6
        GB_INJ(ks1, c1B)         // rounds 5-8:   rot 17,29,16,24
        GA_INJ(ks2, c2B)         // rounds 9-12
        GB_INJ(ks0, c3B)         // rounds 13-16
        GA_INJ(ks1, c4B)         // rounds 17-20
        #pragma unroll
        for (int c = 0; c < 8; c++) b2[c] = x1[c] + c5B;
    }

    // ---- candidates + distance ----
    const uint32_t lvlmask = (1u << i) - 1u;
    const uint32_t flip = 1u << i;
    const float n16  = nrm * 0.0625f;
    const float mnrm = -nrm;

    float vp[8], vm[8];
    #pragma unroll
    for (int c = 0; c < 8; c++) {
        const int o = ori[c];
        const uint32_t D = (b2[c] & lvlmask) ^ flip;        // one LOP3; i==0 -> D=1
        const int cand = o ^ (int)D;                        // sign(cand)==sign(o)
        const uint32_t ax = (uint32_t)(abs(cand) ^ abs(o));
        const int q = __clz(ax + 1u);                       // e = 32 - q
        const float base = fmaf((float)q, n16, mnrm);       // (1 - e/16) * nrm
        // vm = -base unless cand == 0 (then sign(-cand)=+1 -> +base)
        const uint32_t s = (uint32_t)(cand | -cand) & 0x80000000u;
        vp[c] = base;
        vm[c] = __uint_as_float(__float_as_uint(base) ^ s);
    }

    // ---- scatter via precomputed permutation (2x float4 per column) ----
    const int r = (int)(i * 16u + k);
    float* row = out + (size_t)t * (NCOL * TPP) + tp0;
    float* rp = row + (int)P.posP[r] * TPP;
    float* rm = row + (int)P.posM[r] * TPP;
    *(float4*)(rp)     = make_float4(vp[0], vp[1], vp[2], vp[3]);
    *(float4*)(rp + 4) = make_float4(vp[4], vp[5], vp[6], vp[7]);
    *(float4*)(rm)     = make_float4(vm[0], vm[1], vm[2], vm[3]);
    *(float4*)(rm + 4) = make_float4(vm[4], vm[5], vm[6], vm[7]);
    if (r == 0) {
        const float mid = 0.9375f * nrm;       // (1 - 1/16) * norm
        float* rq = row + (int)P.posMid * TPP;
        *(float4*)(rq)     = make_float4(mid, mid, mid, mid);
        *(float4*)(rq + 4) = make_float4(mid, mid, mid, mid);
    }
}

// ---------------------------------------------------------------------------
// Host: derive Threefry keys + 513-column permutation (deterministic).
// ---------------------------------------------------------------------------
extern "C" void kernel_launch(void* const* d_in, const int* in_sizes, int n_in,
                              void* d_out, int out_size) {
    const void* loc = d_in[0];          // locations (EMB, 16)
    const void* in1 = d_in[1];
    const void* in2 = d_in[2];
    float* out = (float*)d_out;

    // key = jax.random.key(42) -> (0, 42); partitionable split(key)[i] = TF(key,(0,i))
    uint32_t kmask0, kmask1, kperm0, kperm1;
    h_tf2x32(0u, 42u, 0u, 0u, kmask0, kmask1);   // kmask
    h_tf2x32(0u, 42u, 0u, 1u, kperm0, kperm1);   // kperm

    // randint(kmask,...): k1,k2 = split(kmask); lower_bits keyed by k2
    uint32_t k2a, k2b;
    h_tf2x32(kmask0, kmask1, 0u, 1u, k2a, k2b);

    // permutation(kperm, 513): one sort round; subkey = split(kperm)[1]
    uint32_t sk0, sk1;
    h_tf2x32(kperm0, kperm1, 0u, 1u, sk0, sk1);

    uint32_t skeys[NCOL];
    int idx[NCOL];
    for (int c = 0; c < NCOL; c++) {
        uint32_t b1, b2;
        h_tf2x32(sk0, sk1, 0u, (uint32_t)c, b1, b2);
        skeys[c] = b1 ^ b2;                    // 32-bit fold of the 64-bit draw
        idx[c] = c;
    }
    std::stable_sort(idx, idx + NCOL,
                     [&](int a, int b) { return skeys[a] < skeys[b]; });
    PermParams P;
    P.posMid = 0; P.pad = 0;
    for (int c = 0; c < NCOL; c++) {
        int p = idx[c];
        if (p < 256)        P.posP[p] = (unsigned short)c;
        else if (p == 256)  P.posMid  = (unsigned short)c;
        else                P.posM[p - 257] = (unsigned short)c;
    }

    // Rotation multipliers, group order (see GA/GB macros):
    RotMuls RM;
    RM.a1 = 1u << 13; RM.a2 = 1u << 15; RM.a3 = 1u << 26; RM.a4 = 1u << 6;
    RM.b1 = 1u << 17; RM.b2 = 1u << 29; RM.b3 = 1u << 16; RM.b4 = 1u << 24;

    const int threads = 256;
    const int blocks = (int)(NTHREADS_TOTAL / threads);   // 4096
    crit_kernel<<<blocks, threads>>>(loc, in1, in2, out, k2a, k2b, RM, P);
}

// round 12
// speedup vs baseline: 1.1200x; 1.1200x over previous
#include <cuda_runtime.h>
#include <cstdint>
#include <algorithm>

// Problem constants
#define TPP  16
#define NCOL 513                      // 2*H*K + 1
#define EMBN 1000000
#define NTHREADS_TOTAL (1u << 20)     // NWORK/8: each thread handles 8 elements

struct PermParams {
    unsigned short posP[256];   // output column of +result[r]
    unsigned short posM[256];   // output column of -result[r]
    unsigned short posMid;      // output column of ori
    unsigned short pad;
};

// Rotation multipliers (1<<R) passed at runtime -> IMAD.WIDE (fma pipe).
// Only the 7 wide rounds need multipliers: rot 13 (GA r1), 17 (GB r1), 24 (GB r4).
struct RotMuls { uint32_t m13, m17, m24; };

// ---------------------------------------------------------------------------
// Threefry-2x32 (host side, for key/permutation derivation)
// ---------------------------------------------------------------------------
static inline uint32_t h_rotl32(uint32_t v, int r) {
    return (v << r) | (v >> (32 - r));
}
#define HTF_R(x0, x1, R) { x0 += x1; x1 = h_rotl32(x1, R) ^ x0; }
static void h_tf2x32(uint32_t k0, uint32_t k1, uint32_t x0, uint32_t x1,
                     uint32_t& o0, uint32_t& o1) {
    const uint32_t ks0 = k0, ks1 = k1, ks2 = k0 ^ k1 ^ 0x1BD11BDAu;
    x0 += ks0; x1 += ks1;
    HTF_R(x0, x1, 13) HTF_R(x0, x1, 15) HTF_R(x0, x1, 26) HTF_R(x0, x1, 6)
    x0 += ks1; x1 += ks2 + 1u;
    HTF_R(x0, x1, 17) HTF_R(x0, x1, 29) HTF_R(x0, x1, 16) HTF_R(x0, x1, 24)
    x0 += ks2; x1 += ks0 + 2u;
    HTF_R(x0, x1, 13) HTF_R(x0, x1, 15) HTF_R(x0, x1, 26) HTF_R(x0, x1, 6)
    x0 += ks0; x1 += ks1 + 3u;
    HTF_R(x0, x1, 17) HTF_R(x0, x1, 29) HTF_R(x0, x1, 16) HTF_R(x0, x1, 24)
    x0 += ks1; x1 += ks2 + 4u;
    HTF_R(x0, x1, 13) HTF_R(x0, x1, 15) HTF_R(x0, x1, 26) HTF_R(x0, x1, 6)
    x0 += ks2; x1 += ks0 + 5u;
    o0 = x0; o1 = x1;
}

// ---------------------------------------------------------------------------
// Main kernel: one thread per 8 adjacent elements (j = 8*tid + c, c=0..7).
// These share (level i, row t, rep k); tp0 in {0, 8}. Shared decode, shared
// gather, shared output columns, float4 stores. Eight interleaved Threefry
// chains at default occupancy (regs 32, occ ~86%).
// Rotate mix 7 WIDE / 13 SHF: IMAD.WIDE costs ~2 fma-pipe slots, so the
// balanced point (slot model validated on R8 vs R11) is x~7 wide rounds:
// ~34 slots per pipe per chain vs 38 (x=15) and 40.5 (x=20).
// Key injections folded into the next round's x0-add (IADD3).
// Level 0 (mask==0) skips Threefry entirely (block-uniform branch).
// Sign property: cand = ori ^ D with D < 2^16 keeps bit31 -> sign(cand) ==
// sign(ori) -> vp = +base; vm = base ^ signbit(cand | -cand).
// ---------------------------------------------------------------------------
__global__ void __launch_bounds__(256)
crit_kernel(const void* __restrict__ loc,
            const void* __restrict__ in1,
            const void* __restrict__ in2,
            float* __restrict__ out,
            uint32_t k2a, uint32_t k2b,
            RotMuls RM, PermParams P) {
    const uint32_t tid = blockIdx.x * 256u + threadIdx.x;
    const uint32_t j0 = tid * 8u;

    const uint32_t tp0 = j0 & 15u;          // 0 or 8
    const uint32_t k   = (j0 >> 4) & 15u;
    const uint32_t t   = (j0 >> 8) & 2047u;
    const uint32_t i   = j0 >> 19;

    // ---- input-layout probe (uniform broadcast loads, L1-hit) ----
    const uint4 A0 = ((const uint4*)in1)[0];
    const uint4 A1 = ((const uint4*)in1)[1];
    const uint4 B0 = ((const uint4*)in2)[0];
    const uint4 B1 = ((const uint4*)in2)[1];
    const uint4 L0 = ((const uint4*)loc)[0];
    const uint4 L1 = ((const uint4*)loc)[1];
    const bool aPos = (A0.x < (1u << 20));  // pos_idx < 2^20; uniform(0,1) bits larger
    const void*  posv = aPos ? in1 : in2;
    const float* nrmp = aPos ? (const float*)in2 : (const float*)in1;
    const uint4 Pw0 = aPos ? A0 : B0;
    const uint4 Pw1 = aPos ? A1 : B1;
    const bool pos64 = ((Pw0.y | Pw0.w | Pw1.y | Pw1.w) == 0u);
    const bool loc64 = (L0.y == 0u || L0.y == 0xFFFFFFFFu) &&
                       (L0.w == 0u || L0.w == 0xFFFFFFFFu) &&
                       (L1.y == 0u || L1.y == 0xFFFFFFFFu) &&
                       (L1.w == 0u || L1.w == 0xFFFFFFFFu);

    long long pidx = pos64 ? ((const long long*)posv)[t]
                           : (long long)((const int*)posv)[t];
    if (pidx < 0) pidx = 0;
    if (pidx >= EMBN) pidx = EMBN - 1;

    int ori[8];
    if (loc64) {
        const size_t base = (size_t)(pidx * TPP + tp0) >> 1;   // longlong2 index
        #pragma unroll
        for (int h = 0; h < 4; h++) {
            const longlong2 L = ((const longlong2*)loc)[base + h];
            ori[2*h]   = (int)L.x;
            ori[2*h+1] = (int)L.y;
        }
    } else {
        const size_t base = (size_t)(pidx * TPP + tp0) >> 2;   // int4 index
        const int4 La = ((const int4*)loc)[base];
        const int4 Lb = ((const int4*)loc)[base + 1];
        ori[0] = La.x; ori[1] = La.y; ori[2] = La.z; ori[3] = La.w;
        ori[4] = Lb.x; ori[5] = Lb.y; ori[6] = Lb.z; ori[7] = Lb.w;
    }
    const float nrm = nrmp[t];

    // ---- oct Threefry-2x32, 20 rounds, injections folded, 7W/13S rotates ----
    const uint32_t ks0 = k2a, ks1 = k2b, ks2 = k2a ^ k2b ^ 0x1BD11BDAu;
    const uint32_t c1B = ks2 + 1u, c2B = ks0 + 2u, c3B = ks1 + 3u,
                   c4B = ks2 + 4u, c5B = ks0 + 5u;

    uint32_t b2[8];
    #pragma unroll
    for (int c = 0; c < 8; c++) b2[c] = 0u;

// Wide rotate round: add + IMAD.WIDE + fused (hi|lo)^x0 LOP3.
#define RW_ALL(M) _Pragma("unroll") for (int c = 0; c < 8; c++) {              \
    x0[c] += x1[c];                                                            \
    uint64_t w_ = (uint64_t)x1[c] * (uint64_t)(M);       /* IMAD.WIDE */       \
    x1[c] = ((uint32_t)(w_ >> 32) | (uint32_t)w_) ^ x0[c]; /* fused LOP3 */    \
}
// Shift rotate round: add + SHF + LOP.
#define RS_ALL(R) _Pragma("unroll") for (int c = 0; c < 8; c++) {              \
    x0[c] += x1[c];                                                            \
    x1[c] = __funnelshift_l(x1[c], x1[c], (R)) ^ x0[c];                        \
}
// Wide round with injection (cA into x0, cB into x1) folded as IADD3.
#define RW_INJ_ALL(M, cA, cB) _Pragma("unroll") for (int c = 0; c < 8; c++) {  \
    x1[c] += (cB);                                                             \
    x0[c] = (x0[c] + (cA)) + x1[c];                      /* IADD3 */           \
    uint64_t w_ = (uint64_t)x1[c] * (uint64_t)(M);                             \
    x1[c] = ((uint32_t)(w_ >> 32) | (uint32_t)w_) ^ x0[c];                     \
}
// GA rotations {13,15,26,6}:  W,S,S,S (1 wide)
// GB rotations {17,29,16,24}: W,S,S,W (2 wide)
#define GA0            RW_ALL(RM.m13)             RS_ALL(15) RS_ALL(26) RS_ALL(6)
#define GA_INJ(cA, cB) RW_INJ_ALL(RM.m13, cA, cB) RS_ALL(15) RS_ALL(26) RS_ALL(6)
#define GB_INJ(cA, cB) RW_INJ_ALL(RM.m17, cA, cB) RS_ALL(29) RS_ALL(16) RW_ALL(RM.m24)

    if (i != 0) {       // level 0 has mask 0: Threefry output unused
        uint32_t x0[8], x1[8];
        #pragma unroll
        for (int c = 0; c < 8; c++) { x0[c] = ks0; x1[c] = (j0 + (uint32_t)c) + ks1; }
        GA0                      // rounds 1-4:   rot 13,15,26,6   (1 wide)
        GB_INJ(ks1, c1B)         // rounds 5-8:   rot 17,29,16,24  (2 wide)
        GA_INJ(ks2, c2B)         // rounds 9-12                    (1 wide)
        GB_INJ(ks0, c3B)         // rounds 13-16                   (2 wide)
        GA_INJ(ks1, c4B)         // rounds 17-20                   (1 wide)
        #pragma unroll
        for (int c = 0; c < 8; c++) b2[c] = x1[c] + c5B;
    }

    // ---- candidates + distance ----
    const uint32_t lvlmask = (1u << i) - 1u;
    const uint32_t flip = 1u << i;
    const float n16  = nrm * 0.0625f;
    const float mnrm = -nrm;

    float vp[8], vm[8];
    #pragma unroll
    for (int c = 0; c < 8; c++) {
        const int o = ori[c];
        const uint32_t D = (b2[c] & lvlmask) ^ flip;        // one LOP3; i==0 -> D=1
        const int cand = o ^ (int)D;                        // sign(cand)==sign(o)
        const uint32_t ax = (uint32_t)(abs(cand) ^ abs(o));
        const int q = __clz(ax + 1u);                       // e = 32 - q
        const float base = fmaf((float)q, n16, mnrm);       // (1 - e/16) * nrm
        // vm = -base unless cand == 0 (then sign(-cand)=+1 -> +base)
        const uint32_t s = (uint32_t)(cand | -cand) & 0x80000000u;
        vp[c] = base;
        vm[c] = __uint_as_float(__float_as_uint(base) ^ s);
    }

    // ---- scatter via precomputed permutation (2x float4 per column) ----
    const int r = (int)(i * 16u + k);
    float* row = out + (size_t)t * (NCOL * TPP) + tp0;
    float* rp = row + (int)P.posP[r] * TPP;
    float* rm = row + (int)P.posM[r] * TPP;
    *(float4*)(rp)     = make_float4(vp[0], vp[1], vp[2], vp[3]);
    *(float4*)(rp + 4) = make_float4(vp[4], vp[5], vp[6], vp[7]);
    *(float4*)(rm)     = make_float4(vm[0], vm[1], vm[2], vm[3]);
    *(float4*)(rm + 4) = make_float4(vm[4], vm[5], vm[6], vm[7]);
    if (r == 0) {
        const float mid = 0.9375f * nrm;       // (1 - 1/16) * norm
        float* rq = row + (int)P.posMid * TPP;
        *(float4*)(rq)     = make_float4(mid, mid, mid, mid);
        *(float4*)(rq + 4) = make_float4(mid, mid, mid, mid);
    }
}

// ---------------------------------------------------------------------------
// Host: derive Threefry keys + 513-column permutation (deterministic).
// ---------------------------------------------------------------------------
extern "C" void kernel_launch(void* const* d_in, const int* in_sizes, int n_in,
                              void* d_out, int out_size) {
    const void* loc = d_in[0];          // locations (EMB, 16)
    const void* in1 = d_in[1];
    const void* in2 = d_in[2];
    float* out = (float*)d_out;

    // key = jax.random.key(42) -> (0, 42); partitionable split(key)[i] = TF(key,(0,i))
    uint32_t kmask0, kmask1, kperm0, kperm1;
    h_tf2x32(0u, 42u, 0u, 0u, kmask0, kmask1);   // kmask
    h_tf2x32(0u, 42u, 0u, 1u, kperm0, kperm1);   // kperm

    // randint(kmask,...): k1,k2 = split(kmask); lower_bits keyed by k2
    uint32_t k2a, k2b;
    h_tf2x32(kmask0, kmask1, 0u, 1u, k2a, k2b);

    // permutation(kperm, 513): one sort round; subkey = split(kperm)[1]
    uint32_t sk0, sk1;
    h_tf2x32(kperm0, kperm1, 0u, 1u, sk0, sk1);

    uint32_t skeys[NCOL];
    int idx[NCOL];
    for (int c = 0; c < NCOL; c++) {
        uint32_t b1, b2;
        h_tf2x32(sk0, sk1, 0u, (uint32_t)c, b1, b2);
        skeys[c] = b1 ^ b2;                    // 32-bit fold of the 64-bit draw
        idx[c] = c;
    }
    std::stable_sort(idx, idx + NCOL,
                     [&](int a, int b) { return skeys[a] < skeys[b]; });
    PermParams P;
    P.posMid = 0; P.pad = 0;
    for (int c = 0; c < NCOL; c++) {
        int p = idx[c];
        if (p < 256)        P.posP[p] = (unsigned short)c;
        else if (p == 256)  P.posMid  = (unsigned short)c;
        else                P.posM[p - 257] = (unsigned short)c;
    }

    RotMuls RM;
    RM.m13 = 1u << 13;
    RM.m17 = 1u << 17;
    RM.m24 = 1u << 24;

    const int threads = 256;
    const int blocks = (int)(NTHREADS_TOTAL / threads);   // 4096
    crit_kernel<<<blocks, threads>>>(loc, in1, in2, out, k2a, k2b, RM, P);
}

// round 13
// speedup vs baseline: 1.1319x; 1.0106x over previous
#include <cuda_runtime.h>
#include <cstdint>
#include <algorithm>

// Problem constants
#define TPP  16
#define NCOL 513                      // 2*H*K + 1
#define EMBN 1000000
#define NTHREADS_TOTAL (1u << 20)     // NWORK/8: each thread handles 8 elements

struct PermParams {
    unsigned short posP[256];   // output column of +result[r]
    unsigned short posM[256];   // output column of -result[r]
    unsigned short posMid;      // output column of ori
    unsigned short pad;
};

// Rotation multipliers (1<<R) passed at runtime -> IMAD.WIDE (fma pipe).
// Wide rounds: rot 13 (GA r1), 17 (GB r1), 24 (GB r4).
struct RotMuls { uint32_t m13, m17, m24; };

// ---------------------------------------------------------------------------
// Threefry-2x32 (host side, for key/permutation derivation)
// ---------------------------------------------------------------------------
static inline uint32_t h_rotl32(uint32_t v, int r) {
    return (v << r) | (v >> (32 - r));
}
#define HTF_R(x0, x1, R) { x0 += x1; x1 = h_rotl32(x1, R) ^ x0; }
static void h_tf2x32(uint32_t k0, uint32_t k1, uint32_t x0, uint32_t x1,
                     uint32_t& o0, uint32_t& o1) {
    const uint32_t ks0 = k0, ks1 = k1, ks2 = k0 ^ k1 ^ 0x1BD11BDAu;
    x0 += ks0; x1 += ks1;
    HTF_R(x0, x1, 13) HTF_R(x0, x1, 15) HTF_R(x0, x1, 26) HTF_R(x0, x1, 6)
    x0 += ks1; x1 += ks2 + 1u;
    HTF_R(x0, x1, 17) HTF_R(x0, x1, 29) HTF_R(x0, x1, 16) HTF_R(x0, x1, 24)
    x0 += ks2; x1 += ks0 + 2u;
    HTF_R(x0, x1, 13) HTF_R(x0, x1, 15) HTF_R(x0, x1, 26) HTF_R(x0, x1, 6)
    x0 += ks0; x1 += ks1 + 3u;
    HTF_R(x0, x1, 17) HTF_R(x0, x1, 29) HTF_R(x0, x1, 16) HTF_R(x0, x1, 24)
    x0 += ks1; x1 += ks2 + 4u;
    HTF_R(x0, x1, 13) HTF_R(x0, x1, 15) HTF_R(x0, x1, 26) HTF_R(x0, x1, 6)
    x0 += ks2; x1 += ks0 + 5u;
    o0 = x0; o1 = x1;
}

// ---------------------------------------------------------------------------
// Main kernel: one thread per 8 adjacent elements (j = 8*tid + c, c=0..7).
// These share (level i, row t, rep k); tp0 in {0, 8}. Shared decode, shared
// gather, shared output columns, float4 stores. Eight interleaved Threefry
// chains at default occupancy (regs 32, occ ~85%).
// Slot model (validated R8/R11/R12): LOP3/SHF/IADD3 -> alu pipe;
// IMAD.WIDE -> 2 fma slots; plain adds land on alu unless forced to IMAD.
// Config: 7 WIDE / 13 SHF rotates + ALL round adds forced to IMAD via
// runtime `one` -> ~41 fma slots vs ~37 alu slots per chain (balanced),
// vs R12's 48 alu / 17 fma.
// Key injections folded into the next round's x0-add (IADD3).
// Level 0 (mask==0) skips Threefry entirely (block-uniform branch).
// Sign property: cand = ori ^ D with D < 2^16 keeps bit31 -> sign(cand) ==
// sign(ori) -> vp = +base; vm = base ^ signbit(cand | -cand).
// ---------------------------------------------------------------------------
__global__ void __launch_bounds__(256)
crit_kernel(const void* __restrict__ loc,
            const void* __restrict__ in1,
            const void* __restrict__ in2,
            float* __restrict__ out,
            uint32_t k2a, uint32_t k2b, uint32_t one,
            RotMuls RM, PermParams P) {
    const uint32_t tid = blockIdx.x * 256u + threadIdx.x;
    const uint32_t j0 = tid * 8u;

    const uint32_t tp0 = j0 & 15u;          // 0 or 8
    const uint32_t k   = (j0 >> 4) & 15u;
    const uint32_t t   = (j0 >> 8) & 2047u;
    const uint32_t i   = j0 >> 19;

    // ---- input-layout probe (uniform broadcast loads, L1-hit) ----
    const uint4 A0 = ((const uint4*)in1)[0];
    const uint4 A1 = ((const uint4*)in1)[1];
    const uint4 B0 = ((const uint4*)in2)[0];
    const uint4 B1 = ((const uint4*)in2)[1];
    const uint4 L0 = ((const uint4*)loc)[0];
    const uint4 L1 = ((const uint4*)loc)[1];
    const bool aPos = (A0.x < (1u << 20));  // pos_idx < 2^20; uniform(0,1) bits larger
    const void*  posv = aPos ? in1 : in2;
    const float* nrmp = aPos ? (const float*)in2 : (const float*)in1;
    const uint4 Pw0 = aPos ? A0 : B0;
    const uint4 Pw1 = aPos ? A1 : B1;
    const bool pos64 = ((Pw0.y | Pw0.w | Pw1.y | Pw1.w) == 0u);
    const bool loc64 = (L0.y == 0u || L0.y == 0xFFFFFFFFu) &&
                       (L0.w == 0u || L0.w == 0xFFFFFFFFu) &&
                       (L1.y == 0u || L1.y == 0xFFFFFFFFu) &&
                       (L1.w == 0u || L1.w == 0xFFFFFFFFu);

    long long pidx = pos64 ? ((const long long*)posv)[t]
                           : (long long)((const int*)posv)[t];
    if (pidx < 0) pidx = 0;
    if (pidx >= EMBN) pidx = EMBN - 1;

    int ori[8];
    if (loc64) {
        const size_t base = (size_t)(pidx * TPP + tp0) >> 1;   // longlong2 index
        #pragma unroll
        for (int h = 0; h < 4; h++) {
            const longlong2 L = ((const longlong2*)loc)[base + h];
            ori[2*h]   = (int)L.x;
            ori[2*h+1] = (int)L.y;
        }
    } else {
        const size_t base = (size_t)(pidx * TPP + tp0) >> 2;   // int4 index
        const int4 La = ((const int4*)loc)[base];
        const int4 Lb = ((const int4*)loc)[base + 1];
        ori[0] = La.x; ori[1] = La.y; ori[2] = La.z; ori[3] = La.w;
        ori[4] = Lb.x; ori[5] = Lb.y; ori[6] = Lb.z; ori[7] = Lb.w;
    }
    const float nrm = nrmp[t];

    // ---- oct Threefry-2x32, 20 rounds, injections folded, 7W/13S rotates ----
    const uint32_t ks0 = k2a, ks1 = k2b, ks2 = k2a ^ k2b ^ 0x1BD11BDAu;
    const uint32_t c1B = ks2 + 1u, c2B = ks0 + 2u, c3B = ks1 + 3u,
                   c4B = ks2 + 4u, c5B = ks0 + 5u;

    uint32_t b2[8];
    #pragma unroll
    for (int c = 0; c < 8; c++) b2[c] = 0u;

#define QADD(a, b) ((a) * one + (b))                     /* forced IMAD, fma */
// Wide rotate round: IMAD add + IMAD.WIDE + fused (hi|lo)^x0 LOP3.
#define RW_ALL(M) _Pragma("unroll") for (int c = 0; c < 8; c++) {              \
    x0[c] = QADD(x0[c], x1[c]);                                                \
    uint64_t w_ = (uint64_t)x1[c] * (uint64_t)(M);       /* IMAD.WIDE */       \
    x1[c] = ((uint32_t)(w_ >> 32) | (uint32_t)w_) ^ x0[c]; /* fused LOP3 */    \
}
// Shift rotate round: IMAD add + SHF + LOP.
#define RS_ALL(R) _Pragma("unroll") for (int c = 0; c < 8; c++) {              \
    x0[c] = QADD(x0[c], x1[c]);                                                \
    x1[c] = __funnelshift_l(x1[c], x1[c], (R)) ^ x0[c];                        \
}
// Wide round with injection (cA into x0, cB into x1): x1 add as IMAD,
// x0 double-add folded as IADD3 (alu).
#define RW_INJ_ALL(M, cA, cB) _Pragma("unroll") for (int c = 0; c < 8; c++) {  \
    x1[c] = QADD(x1[c], (cB));                                                 \
    x0[c] = (x0[c] + (cA)) + x1[c];                      /* IADD3 */           \
    uint64_t w_ = (uint64_t)x1[c] * (uint64_t)(M);                             \
    x1[c] = ((uint32_t)(w_ >> 32) | (uint32_t)w_) ^ x0[c];                     \
}
// GA rotations {13,15,26,6}:  W,S,S,S (1 wide)
// GB rotations {17,29,16,24}: W,S,S,W (2 wide)
#define GA0            RW_ALL(RM.m13)             RS_ALL(15) RS_ALL(26) RS_ALL(6)
#define GA_INJ(cA, cB) RW_INJ_ALL(RM.m13, cA, cB) RS_ALL(15) RS_ALL(26) RS_ALL(6)
#define GB_INJ(cA, cB) RW_INJ_ALL(RM.m17, cA, cB) RS_ALL(29) RS_ALL(16) RW_ALL(RM.m24)

    if (i != 0) {       // level 0 has mask 0: Threefry output unused
        uint32_t x0[8], x1[8];
        #pragma unroll
        for (int c = 0; c < 8; c++) { x0[c] = ks0; x1[c] = (j0 + (uint32_t)c) + ks1; }
        GA0                      // rounds 1-4:   rot 13,15,26,6   (1 wide)
        GB_INJ(ks1, c1B)         // rounds 5-8:   rot 17,29,16,24  (2 wide)
        GA_INJ(ks2, c2B)         // rounds 9-12                    (1 wide)
        GB_INJ(ks0, c3B)         // rounds 13-16                   (2 wide)
        GA_INJ(ks1, c4B)         // rounds 17-20                   (1 wide)
        #pragma unroll
        for (int c = 0; c < 8; c++) b2[c] = QADD(x1[c], c5B);
    }

    // ---- candidates + distance ----
    const uint32_t lvlmask = (1u << i) - 1u;
    const uint32_t flip = 1u << i;
    const float n16  = nrm * 0.0625f;
    const float mnrm = -nrm;

    float vp[8], vm[8];
    #pragma unroll
    for (int c = 0; c < 8; c++) {
        const int o = ori[c];
        const uint32_t D = (b2[c] & lvlmask) ^ flip;        // one LOP3; i==0 -> D=1
        const int cand = o ^ (int)D;                        // sign(cand)==sign(o)
        const uint32_t ax = (uint32_t)(abs(cand) ^ abs(o));
        const int q = __clz(ax + 1u);                       // e = 32 - q
        const float base = fmaf((float)q, n16, mnrm);       // (1 - e/16) * nrm
        // vm = -base unless cand == 0 (then sign(-cand)=+1 -> +base)
        const uint32_t s = (uint32_t)(cand | -cand) & 0x80000000u;
        vp[c] = base;
        vm[c] = __uint_as_float(__float_as_uint(base) ^ s);
    }

    // ---- scatter via precomputed permutation (2x float4 per column) ----
    const int r = (int)(i * 16u + k);
    float* row = out + (size_t)t * (NCOL * TPP) + tp0;
    float* rp = row + (int)P.posP[r] * TPP;
    float* rm = row + (int)P.posM[r] * TPP;
    *(float4*)(rp)     = make_float4(vp[0], vp[1], vp[2], vp[3]);
    *(float4*)(rp + 4) = make_float4(vp[4], vp[5], vp[6], vp[7]);
    *(float4*)(rm)     = make_float4(vm[0], vm[1], vm[2], vm[3]);
    *(float4*)(rm + 4) = make_float4(vm[4], vm[5], vm[6], vm[7]);
    if (r == 0) {
        const float mid = 0.9375f * nrm;       // (1 - 1/16) * norm
        float* rq = row + (int)P.posMid * TPP;
        *(float4*)(rq)     = make_float4(mid, mid, mid, mid);
        *(float4*)(rq + 4) = make_float4(mid, mid, mid, mid);
    }
}

// ---------------------------------------------------------------------------
// Host: derive Threefry keys + 513-column permutation (deterministic).
// ---------------------------------------------------------------------------
extern "C" void kernel_launch(void* const* d_in, const int* in_sizes, int n_in,
                              void* d_out, int out_size) {
    const void* loc = d_in[0];          // locations (EMB, 16)
    const void* in1 = d_in[1];
    const void* in2 = d_in[2];
    float* out = (float*)d_out;

    // key = jax.random.key(42) -> (0, 42); partitionable split(key)[i] = TF(key,(0,i))
    uint32_t kmask0, kmask1, kperm0, kperm1;
    h_tf2x32(0u, 42u, 0u, 0u, kmask0, kmask1);   // kmask
    h_tf2x32(0u, 42u, 0u, 1u, kperm0, kperm1);   // kperm

    // randint(kmask,...): k1,k2 = split(kmask); lower_bits keyed by k2
    uint32_t k2a, k2b;
    h_tf2x32(kmask0, kmask1, 0u, 1u, k2a, k2b);

    // permutation(kperm, 513): one sort round; subkey = split(kperm)[1]
    uint32_t sk0, sk1;
    h_tf2x32(kperm0, kperm1, 0u, 1u, sk0, sk1);

    uint32_t skeys[NCOL];
    int idx[NCOL];
    for (int c = 0; c < NCOL; c++) {
        uint32_t b1, b2;
        h_tf2x32(sk0, sk1, 0u, (uint32_t)c, b1, b2);
        skeys[c] = b1 ^ b2;                    // 32-bit fold of the 64-bit draw
        idx[c] = c;
    }
    std::stable_sort(idx, idx + NCOL,
                     [&](int a, int b) { return skeys[a] < skeys[b]; });
    PermParams P;
    P.posMid = 0; P.pad = 0;
    for (int c = 0; c < NCOL; c++) {
        int p = idx[c];
        if (p < 256)        P.posP[p] = (unsigned short)c;
        else if (p == 256)  P.posMid  = (unsigned short)c;
        else                P.posM[p - 257] = (unsigned short)c;
    }

    RotMuls RM;
    RM.m13 = 1u << 13;
    RM.m17 = 1u << 17;
    RM.m24 = 1u << 24;

    const int threads = 256;
    const int blocks = (int)(NTHREADS_TOTAL / threads);   // 4096
    crit_kernel<<<blocks, threads>>>(loc, in1, in2, out, k2a, k2b, 1u, RM, P);
}